// round 10
// baseline (speedup 1.0000x reference)
#include <cuda_runtime.h>
#include <cuda_bf16.h>
#include <cstdint>

#define NTOK 16384
#define MD   2048
#define PD   256
#define NE   64
#define BK   32
#define NBLK 148
#define BMP  112     // padded rows per block (7 strips of 16)

// ---------------- device globals ----------------
__device__ __align__(16) __nv_bfloat16 g_Whi[PD * MD];
__device__ __align__(16) __nv_bfloat16 g_Wlo[PD * MD];
__device__ __align__(16) __nv_bfloat16 g_simHi[NE * PD];
__device__ __align__(16) __nv_bfloat16 g_simLo[NE * PD];
__device__ float g_scale;
__device__ float g_active;

// ---------------- helpers ----------------
__device__ __forceinline__ uint32_t smem_u32(const void* p) {
    uint32_t a;
    asm("{ .reg .u64 t; cvta.to.shared.u64 t, %1; cvt.u32.u64 %0, t; }" : "=r"(a) : "l"(p));
    return a;
}
#define LDSM4(r0, r1, r2, r3, a)                                                  \
    asm volatile("ldmatrix.sync.aligned.m8n8.x4.shared.b16 {%0,%1,%2,%3}, [%4];" \
                 : "=r"(r0), "=r"(r1), "=r"(r2), "=r"(r3) : "r"(a))
#define MMA16816(c, a, b)                                                         \
    asm volatile("mma.sync.aligned.m16n8k16.row.col.f32.bf16.bf16.f32 "           \
                 "{%0,%1,%2,%3}, {%4,%5,%6,%7}, {%8,%9}, {%0,%1,%2,%3};"          \
                 : "+f"((c)[0]), "+f"((c)[1]), "+f"((c)[2]), "+f"((c)[3])         \
                 : "r"((a)[0]), "r"((a)[1]), "r"((a)[2]), "r"((a)[3]),            \
                   "r"((b)[0]), "r"((b)[1]))
#define CP16(dst, src) asm volatile("cp.async.cg.shared.global [%0], [%1], 16;" :: "r"(dst), "l"(src))
#define CP_COMMIT()    asm volatile("cp.async.commit_group;" ::: "memory")
#define CP_WAIT0()     asm volatile("cp.async.wait_group 0;" ::: "memory")

__device__ __forceinline__ uint32_t pack_hi(float v0, float v1, float& l0, float& l1) {
    __nv_bfloat16 h0 = __float2bfloat16(v0), h1 = __float2bfloat16(v1);
    l0 = v0 - __bfloat162float(h0);
    l1 = v1 - __bfloat162float(h1);
    return (uint32_t)__bfloat16_as_ushort(h0) | ((uint32_t)__bfloat16_as_ushort(h1) << 16);
}
__device__ __forceinline__ uint32_t pack_bf2(float v0, float v1) {
    return (uint32_t)__bfloat16_as_ushort(__float2bfloat16(v0)) |
           ((uint32_t)__bfloat16_as_ushort(__float2bfloat16(v1)) << 16);
}

// ---------------- prep kernels ----------------
__global__ void convert_w_kernel(const float* __restrict__ W) {
    int i = blockIdx.x * 256 + threadIdx.x;     // 131072 float4 chunks
    float4 v = ((const float4*)W)[i];
    float l0, l1, l2, l3;
    uint32_t h0 = pack_hi(v.x, v.y, l0, l1);
    uint32_t h1 = pack_hi(v.z, v.w, l2, l3);
    ((uint2*)g_Whi)[i] = make_uint2(h0, h1);
    ((uint2*)g_Wlo)[i] = make_uint2(pack_bf2(l0, l1), pack_bf2(l2, l3));
}
__global__ void prep_kernel(const float* __restrict__ sim,
                            const float* __restrict__ temperature,
                            const float* __restrict__ mask) {
    int e = threadIdx.x;  // 0..63
    float ss = 0.f;
    #pragma unroll 8
    for (int p = 0; p < PD; p++) {
        float v = sim[p * NE + e];
        ss += v * v;
    }
    float inv = 1.f / fmaxf(sqrtf(ss), 1e-12f);
    #pragma unroll 4
    for (int p = 0; p < PD; p++) {
        float v = sim[p * NE + e] * inv;
        __nv_bfloat16 h = __float2bfloat16(v);
        g_simHi[e * PD + p] = h;
        g_simLo[e * PD + p] = __float2bfloat16(v - __bfloat162float(h));
    }
    if (e == 0) {
        float a = 0.f;
        for (int i = 0; i < NE; i++) a += mask[i];
        g_active = a;
        g_scale = expf(fminf(temperature[0], 4.6051701859880913680f));
    }
}

// ---------------- smem layout (bytes) ----------------
// mainloop stage: Ahi 8960 | Alo 8960 | Bhi 20480 | Blo 20480 = 58880; x2 stages
#define G1_AHI 0
#define G1_ALO 8960
#define G1_BHI 17920
#define G1_BLO 38400
#define G1_STAGE 58880
// tail overlay:
#define SHI_B   0          // 64 x 264 elems x 2B = 33792
#define SLO_B   33792
#define SC_B    67584      // 112 x 68 f32 = 30464
#define BIAS_B  98048      // 256 f32
#define MASK_B  99072      // 64 f32
#define SMEM_TOTAL (2 * G1_STAGE)   // 117760

// ---------------- fused kernel ----------------
__global__ void __launch_bounds__(256, 1)
fused_kernel(const float* __restrict__ X, const float* __restrict__ bias,
             const float* __restrict__ mask,
             float* __restrict__ out_logits, float* __restrict__ out_topk,
             int write_topk) {
    extern __shared__ __align__(16) char dsm[];
    const uint32_t sb = smem_u32(dsm);

    const int tid = threadIdx.x;
    const int wid = tid >> 5, lane = tid & 31;
    const int blk = blockIdx.x;
    const int tokBase = (blk * NTOK) / NBLK;
    const int valid   = ((blk + 1) * NTOK) / NBLK - tokBase;

    const uint32_t aRow  = (uint32_t)(lane & 15);
    const uint32_t aByte = (uint32_t)((lane >> 4) * 16);
    const int gq = lane >> 3;
    const uint32_t bRowBase = (uint32_t)(((gq >> 1) << 3) + (lane & 7));
    const uint32_t bByte = (uint32_t)((gq & 1) * 16);

    const int aRowL = tid >> 3, aC4 = (tid & 7) * 4;   // A chunks: 896 total
    const int bRowL = tid >> 2, bC8 = (tid & 3) * 8;   // B rows: + i*64

    // acc: 16 rows (this warp's strip) x 256 cols = 128 f32/lane
    float acc[32][4];
    #pragma unroll
    for (int j = 0; j < 32; j++)
        #pragma unroll
        for (int q = 0; q < 4; q++) acc[j][q] = 0.f;

    // clamped global row for A loads
    int aGRow[4];
    #pragma unroll
    for (int i = 0; i < 4; i++) {
        int r = aRowL + i * 32;
        int t = tokBase + (r < BMP ? r : BMP - 1);
        aGRow[i] = t < NTOK ? t : NTOK - 1;
    }

    float4 aReg[4];
    #pragma unroll
    for (int i = 0; i < 4; i++)
        if (i * 256 + tid < 896)
            aReg[i] = *(const float4*)(X + (size_t)aGRow[i] * MD + aC4);
    #pragma unroll
    for (int i = 0; i < 4; i++) {
        int row = bRowL + i * 64;
        CP16(sb + G1_BHI + (uint32_t)(row * 80 + bC8 * 2), g_Whi + (size_t)row * MD + bC8);
        CP16(sb + G1_BLO + (uint32_t)(row * 80 + bC8 * 2), g_Wlo + (size_t)row * MD + bC8);
    }
    CP_COMMIT();

    // ================= mainloop =================
    for (int kc = 0; kc < MD / BK; kc++) {
        const int s = kc & 1;
        char* st = dsm + s * G1_STAGE;
        const uint32_t stu = sb + s * G1_STAGE;

        #pragma unroll
        for (int i = 0; i < 4; i++) {
            if (i * 256 + tid < 896) {
                float4 v = aReg[i];
                float l0, l1, l2, l3;
                uint32_t ph0 = pack_hi(v.x, v.y, l0, l1);
                uint32_t ph1 = pack_hi(v.z, v.w, l2, l3);
                int row = aRowL + i * 32;
                *(uint2*)(st + G1_AHI + row * 80 + aC4 * 2) = make_uint2(ph0, ph1);
                *(uint2*)(st + G1_ALO + row * 80 + aC4 * 2) =
                    make_uint2(pack_bf2(l0, l1), pack_bf2(l2, l3));
            }
        }
        CP_WAIT0();
        __syncthreads();

        if (kc + 1 < MD / BK) {
            const int k0n = (kc + 1) * BK;
            #pragma unroll
            for (int i = 0; i < 4; i++)
                if (i * 256 + tid < 896)
                    aReg[i] = *(const float4*)(X + (size_t)aGRow[i] * MD + k0n + aC4);
            const uint32_t stn = sb + (s ^ 1) * G1_STAGE;
            #pragma unroll
            for (int i = 0; i < 4; i++) {
                int row = bRowL + i * 64;
                CP16(stn + G1_BHI + (uint32_t)(row * 80 + bC8 * 2),
                     g_Whi + (size_t)row * MD + k0n + bC8);
                CP16(stn + G1_BLO + (uint32_t)(row * 80 + bC8 * 2),
                     g_Wlo + (size_t)row * MD + k0n + bC8);
            }
            CP_COMMIT();
        }

        if (wid < 7) {
            #pragma unroll
            for (int ks = 0; ks < 2; ks++) {
                uint32_t ahi[4], alo[4];
                uint32_t aoff = (uint32_t)((wid * 16 + aRow) * 80) +
                                (uint32_t)(ks * 32) + aByte;
                LDSM4(ahi[0], ahi[1], ahi[2], ahi[3], stu + G1_AHI + aoff);
                LDSM4(alo[0], alo[1], alo[2], alo[3], stu + G1_ALO + aoff);
                #pragma unroll
                for (int p = 0; p < 8; p++) {
                    uint32_t bh[2][4], bl[2][4];
                    #pragma unroll
                    for (int j = 0; j < 2; j++) {
                        int nf2 = p * 2 + j;
                        uint32_t off = (uint32_t)((nf2 * 16 + bRowBase) * 80) +
                                       (uint32_t)(ks * 32) + bByte;
                        LDSM4(bh[j][0], bh[j][1], bh[j][2], bh[j][3], stu + G1_BHI + off);
                        LDSM4(bl[j][0], bl[j][1], bl[j][2], bl[j][3], stu + G1_BLO + off);
                    }
                    #pragma unroll
                    for (int j = 0; j < 2; j++)
                        #pragma unroll
                        for (int half = 0; half < 2; half++) {
                            int nf = (p * 2 + j) * 2 + half;
                            uint32_t b2[2] = { bh[j][half * 2], bh[j][half * 2 + 1] };
                            MMA16816(acc[nf], ahi, b2);
                        }
                    #pragma unroll
                    for (int j = 0; j < 2; j++)
                        #pragma unroll
                        for (int half = 0; half < 2; half++) {
                            int nf = (p * 2 + j) * 2 + half;
                            uint32_t b2[2] = { bl[j][half * 2], bl[j][half * 2 + 1] };
                            MMA16816(acc[nf], ahi, b2);
                        }
                    #pragma unroll
                    for (int j = 0; j < 2; j++)
                        #pragma unroll
                        for (int half = 0; half < 2; half++) {
                            int nf = (p * 2 + j) * 2 + half;
                            uint32_t b2[2] = { bh[j][half * 2], bh[j][half * 2 + 1] };
                            MMA16816(acc[nf], alo, b2);
                        }
                }
            }
        }
    }

    // ================= fused tail =================
    __syncthreads();  // stage smem now dead

    #pragma unroll
    for (int i = 0; i < 8; i++) {
        int idx = i * 256 + tid;
        int row = idx >> 5, c8 = (idx & 31) * 8;
        *(uint4*)(dsm + SHI_B + row * 528 + c8 * 2) = *(const uint4*)(g_simHi + row * PD + c8);
        *(uint4*)(dsm + SLO_B + row * 528 + c8 * 2) = *(const uint4*)(g_simLo + row * PD + c8);
    }
    ((float*)(dsm + BIAS_B))[tid] = bias[tid];
    if (tid < NE) ((float*)(dsm + MASK_B))[tid] = mask[tid];
    __syncthreads();

    const int qr = lane >> 2, qc = (lane & 3) * 2;

    if (wid < 7) {
        // bias add + row-norm (quad reduce; rows wid*16+qr, +8)
        const float* sBias = (const float*)(dsm + BIAS_B);
        float ss0 = 0.f, ss1 = 0.f;
        #pragma unroll
        for (int nf = 0; nf < 32; nf++) {
            int c = nf * 8 + qc;
            float b0 = sBias[c], b1 = sBias[c + 1];
            acc[nf][0] += b0; acc[nf][1] += b1;
            acc[nf][2] += b0; acc[nf][3] += b1;
            ss0 += acc[nf][0] * acc[nf][0] + acc[nf][1] * acc[nf][1];
            ss1 += acc[nf][2] * acc[nf][2] + acc[nf][3] * acc[nf][3];
        }
        ss0 += __shfl_xor_sync(0xffffffffu, ss0, 1);
        ss0 += __shfl_xor_sync(0xffffffffu, ss0, 2);
        ss1 += __shfl_xor_sync(0xffffffffu, ss1, 1);
        ss1 += __shfl_xor_sync(0xffffffffu, ss1, 2);
        const float scale = g_scale;
        const float inv0 = scale / fmaxf(sqrtf(ss0), 1e-12f);
        const float inv1 = scale / fmaxf(sqrtf(ss1), 1e-12f);

        // GEMM2: this warp's 16 rows x 64 experts, full K=256, 3-term split
        float acc2[8][4];
        #pragma unroll
        for (int j = 0; j < 8; j++)
            #pragma unroll
            for (int q = 0; q < 4; q++) acc2[j][q] = 0.f;

        #pragma unroll 4
        for (int g = 0; g < 16; g++) {
            uint32_t ahi[4], alo[4];
            float l0, l1;
            ahi[0] = pack_hi(acc[2 * g][0],     acc[2 * g][1],     l0, l1); alo[0] = pack_bf2(l0, l1);
            ahi[1] = pack_hi(acc[2 * g][2],     acc[2 * g][3],     l0, l1); alo[1] = pack_bf2(l0, l1);
            ahi[2] = pack_hi(acc[2 * g + 1][0], acc[2 * g + 1][1], l0, l1); alo[2] = pack_bf2(l0, l1);
            ahi[3] = pack_hi(acc[2 * g + 1][2], acc[2 * g + 1][3], l0, l1); alo[3] = pack_bf2(l0, l1);
            #pragma unroll
            for (int ne2 = 0; ne2 < 4; ne2++) {
                uint32_t boff = (uint32_t)((ne2 * 16 + bRowBase) * 528) +
                                (uint32_t)(g * 32) + bByte;
                uint32_t bh[4], bl[4];
                LDSM4(bh[0], bh[1], bh[2], bh[3], sb + SHI_B + boff);
                LDSM4(bl[0], bl[1], bl[2], bl[3], sb + SLO_B + boff);
                #pragma unroll
                for (int half = 0; half < 2; half++) {
                    uint32_t b2[2] = { bh[half * 2], bh[half * 2 + 1] };
                    MMA16816(acc2[ne2 * 2 + half], ahi, b2);
                }
                #pragma unroll
                for (int half = 0; half < 2; half++) {
                    uint32_t b2[2] = { bl[half * 2], bl[half * 2 + 1] };
                    MMA16816(acc2[ne2 * 2 + half], ahi, b2);
                }
                #pragma unroll
                for (int half = 0; half < 2; half++) {
                    uint32_t b2[2] = { bh[half * 2], bh[half * 2 + 1] };
                    MMA16816(acc2[ne2 * 2 + half], alo, b2);
                }
            }
        }

        // scale, mask, store logits, softmax -> SC
        const float* sMask = (const float*)(dsm + MASK_B);
        const int r0 = wid * 16 + qr, r1 = r0 + 8;
        float p0[16], p1[16];
        #pragma unroll
        for (int nf = 0; nf < 8; nf++) {
            int c = nf * 8 + qc;
            bool m0 = sMask[c] == 0.f, m1 = sMask[c + 1] == 0.f;
            float a  = m0 ? -1e9f : acc2[nf][0] * inv0;
            float b  = m1 ? -1e9f : acc2[nf][1] * inv0;
            float cc = m0 ? -1e9f : acc2[nf][2] * inv1;
            float dd = m1 ? -1e9f : acc2[nf][3] * inv1;
            p0[nf * 2] = a;  p0[nf * 2 + 1] = b;
            p1[nf * 2] = cc; p1[nf * 2 + 1] = dd;
            if (r0 < valid)
                *(float2*)(out_logits + (size_t)(tokBase + r0) * NE + c) = make_float2(a, b);
            if (r1 < valid)
                *(float2*)(out_logits + (size_t)(tokBase + r1) * NE + c) = make_float2(cc, dd);
        }
        if (write_topk) {
            float m0 = -1e30f, m1 = -1e30f;
            #pragma unroll
            for (int j = 0; j < 16; j++) { m0 = fmaxf(m0, p0[j]); m1 = fmaxf(m1, p1[j]); }
            #pragma unroll
            for (int o = 1; o < 4; o <<= 1) {
                m0 = fmaxf(m0, __shfl_xor_sync(0xffffffffu, m0, o));
                m1 = fmaxf(m1, __shfl_xor_sync(0xffffffffu, m1, o));
            }
            float s0 = 0.f, s1 = 0.f;
            #pragma unroll
            for (int j = 0; j < 16; j++) {
                p0[j] = __expf(p0[j] - m0); s0 += p0[j];
                p1[j] = __expf(p1[j] - m1); s1 += p1[j];
            }
            #pragma unroll
            for (int o = 1; o < 4; o <<= 1) {
                s0 += __shfl_xor_sync(0xffffffffu, s0, o);
                s1 += __shfl_xor_sync(0xffffffffu, s1, o);
            }
            float is0 = 1.f / s0, is1 = 1.f / s1;
            float* sc = (float*)(dsm + SC_B);
            #pragma unroll
            for (int nf = 0; nf < 8; nf++) {
                int c = nf * 8 + qc;
                *(float2*)(sc + r0 * 68 + c) =
                    make_float2(p0[nf * 2] * is0 + 1e-14f, p0[nf * 2 + 1] * is0 + 1e-14f);
                *(float2*)(sc + r1 * 68 + c) =
                    make_float2(p1[nf * 2] * is1 + 1e-14f, p1[nf * 2 + 1] * is1 + 1e-14f);
            }
        }
    }
    __syncthreads();

    if (write_topk && tid < valid) {
        const float* row = (const float*)(dsm + SC_B) + tid * 68;
        float v[64];
        #pragma unroll
        for (int i = 0; i < 16; i++)
            *(float4*)(v + i * 4) = *(const float4*)(row + i * 4);
        #pragma unroll 2
        for (int k = 2; k <= 64; k <<= 1)
            #pragma unroll 2
            for (int j = k >> 1; j > 0; j >>= 1)
                #pragma unroll
                for (int i = 0; i < 64; i++) {
                    int p = i ^ j;
                    if (p > i) {
                        bool up = ((i & k) == 0);
                        float a = v[i], b = v[p];
                        bool sw = up ? (a > b) : (a < b);
                        float lo = sw ? b : a, hi = sw ? a : b;
                        v[i] = lo; v[p] = hi;
                    }
                }
        float cum = 0.f; int k = 0;
        #pragma unroll
        for (int r = 63; r >= 0; r--) { if (cum < 1.f) k++; cum += v[r]; }
        out_topk[tokBase + tid] = fminf((float)k, g_active);
    }
}

// ---------------- launch ----------------
extern "C" void kernel_launch(void* const* d_in, const int* in_sizes, int n_in,
                              void* d_out, int out_size) {
    const float* x    = (const float*)d_in[0];
    const float* W    = (const float*)d_in[1];
    const float* b    = (const float*)d_in[2];
    const float* sim  = (const float*)d_in[3];
    const float* temp = (const float*)d_in[4];
    const float* mask = (const float*)d_in[5];
    float* out = (float*)d_out;

    cudaFuncSetAttribute(fused_kernel, cudaFuncAttributeMaxDynamicSharedMemorySize, SMEM_TOTAL);

    convert_w_kernel<<<512, 256>>>(W);
    prep_kernel<<<1, 64>>>(sim, temp, mask);

    const int logits_elems = NTOK * NE;
    int write_topk = (out_size >= logits_elems + NTOK) ? 1 : 0;
    fused_kernel<<<NBLK, 256, SMEM_TOTAL>>>(x, b, mask, out, out + logits_elems, write_topk);
}

// round 12
// speedup vs baseline: 4.0871x; 4.0871x over previous
#include <cuda_runtime.h>
#include <cuda_bf16.h>
#include <cuda_fp16.h>
#include <cstdint>

#define NTOK 16384
#define MD   2048
#define PD   256
#define NE   64
#define BK   32

// ---------------- device globals ----------------
__device__ __align__(16) __half g_Wh[PD * MD];
__device__ __align__(16) __nv_bfloat16 g_simHi[NE * PD];
__device__ __align__(16) __nv_bfloat16 g_simLo[NE * PD];
__device__ float g_scale;
__device__ float g_active;

// ---------------- helpers ----------------
__device__ __forceinline__ uint32_t smem_u32(const void* p) {
    uint32_t a;
    asm("{ .reg .u64 t; cvta.to.shared.u64 t, %1; cvt.u32.u64 %0, t; }" : "=r"(a) : "l"(p));
    return a;
}
#define LDSM4(r0, r1, r2, r3, a)                                                  \
    asm volatile("ldmatrix.sync.aligned.m8n8.x4.shared.b16 {%0,%1,%2,%3}, [%4];" \
                 : "=r"(r0), "=r"(r1), "=r"(r2), "=r"(r3) : "r"(a))
#define MMAB16(c, a, b)                                                           \
    asm volatile("mma.sync.aligned.m16n8k16.row.col.f32.bf16.bf16.f32 "           \
                 "{%0,%1,%2,%3}, {%4,%5,%6,%7}, {%8,%9}, {%0,%1,%2,%3};"          \
                 : "+f"((c)[0]), "+f"((c)[1]), "+f"((c)[2]), "+f"((c)[3])         \
                 : "r"((a)[0]), "r"((a)[1]), "r"((a)[2]), "r"((a)[3]),            \
                   "r"((b)[0]), "r"((b)[1]))
#define MMAF16(c, a, b)                                                           \
    asm volatile("mma.sync.aligned.m16n8k16.row.col.f32.f16.f16.f32 "             \
                 "{%0,%1,%2,%3}, {%4,%5,%6,%7}, {%8,%9}, {%0,%1,%2,%3};"          \
                 : "+f"((c)[0]), "+f"((c)[1]), "+f"((c)[2]), "+f"((c)[3])         \
                 : "r"((a)[0]), "r"((a)[1]), "r"((a)[2]), "r"((a)[3]),            \
                   "r"((b)[0]), "r"((b)[1]))
#define CP16(dst, src) asm volatile("cp.async.cg.shared.global [%0], [%1], 16;" :: "r"(dst), "l"(src))
#define CP_COMMIT()    asm volatile("cp.async.commit_group;" ::: "memory")
#define CP_WAIT0()     asm volatile("cp.async.wait_group 0;" ::: "memory")

__device__ __forceinline__ uint32_t pack_h2(float a, float b) {
    __half2 t = __floats2half2_rn(a, b);
    return *reinterpret_cast<uint32_t*>(&t);
}
__device__ __forceinline__ uint32_t pack_hi(float v0, float v1, float& l0, float& l1) {
    __nv_bfloat16 h0 = __float2bfloat16(v0), h1 = __float2bfloat16(v1);
    l0 = v0 - __bfloat162float(h0);
    l1 = v1 - __bfloat162float(h1);
    return (uint32_t)__bfloat16_as_ushort(h0) | ((uint32_t)__bfloat16_as_ushort(h1) << 16);
}
__device__ __forceinline__ uint32_t pack_bf2(float v0, float v1) {
    return (uint32_t)__bfloat16_as_ushort(__float2bfloat16(v0)) |
           ((uint32_t)__bfloat16_as_ushort(__float2bfloat16(v1)) << 16);
}

// ---------------- prep kernels ----------------
__global__ void convert_w_kernel(const float* __restrict__ W) {
    int i = blockIdx.x * 256 + threadIdx.x;     // 131072 float4 chunks
    float4 v = ((const float4*)W)[i];
    ((uint2*)g_Wh)[i] = make_uint2(pack_h2(v.x, v.y), pack_h2(v.z, v.w));
}
__global__ void prep_kernel(const float* __restrict__ sim,
                            const float* __restrict__ temperature,
                            const float* __restrict__ mask) {
    int e = threadIdx.x;  // 0..63
    float ss = 0.f;
    #pragma unroll 8
    for (int p = 0; p < PD; p++) {
        float v = sim[p * NE + e];
        ss += v * v;
    }
    float inv = 1.f / fmaxf(sqrtf(ss), 1e-12f);
    #pragma unroll 4
    for (int p = 0; p < PD; p++) {
        float v = sim[p * NE + e] * inv;
        __nv_bfloat16 h = __float2bfloat16(v);
        g_simHi[e * PD + p] = h;
        g_simLo[e * PD + p] = __float2bfloat16(v - __bfloat162float(h));
    }
    if (e == 0) {
        float a = 0.f;
        for (int i = 0; i < NE; i++) a += mask[i];
        g_active = a;
        g_scale = expf(fminf(temperature[0], 4.6051701859880913680f));
    }
}

// ---------------- smem layout (bytes) ----------------
// mainloop: 2 stages of (A 10240 | B 20480)
#define G1_A 0
#define G1_B 10240
#define G1_STAGE 30720
// tail overlay:
#define SHI_B   0          // sim hi: 64 rows x 264 elems x 2B = 33792
#define SLO_B   33792
#define CBUF_B  67584      // 128 x 68 f32 = 34816
#define SCBUF_B 102400     // 128 x 68 f32 = 34816 (end 137216)
#define BIAS_B  137216     // 256 f32
#define MASK_B  138240     // 64 f32
#define NORM_B  138496     // 128 x 2 f32
#define SINV_B  139520     // 128 f32
#define SMEM_TOTAL 140032

// ---------------- fused kernel ----------------
__global__ void __launch_bounds__(256, 1)
fused_kernel(const float* __restrict__ X, const float* __restrict__ bias,
             const float* __restrict__ mask,
             float* __restrict__ out_logits, float* __restrict__ out_topk,
             int write_topk) {
    extern __shared__ __align__(16) char dsm[];
    const uint32_t sb = smem_u32(dsm);

    const int tid = threadIdx.x;
    const int wid = tid >> 5, lane = tid & 31;
    const int warpM = wid & 3;    // 4 x 32 rows
    const int warpN = wid >> 2;   // 2 x 128 cols
    const int by = blockIdx.x;
    const int tokBase = by * 128;

    const uint32_t aRow  = (uint32_t)(lane & 15);
    const uint32_t aByte = (uint32_t)((lane >> 4) * 16);
    const int gq = lane >> 3;
    const uint32_t bRowBase = (uint32_t)(((gq >> 1) << 3) + (lane & 7));
    const uint32_t bByte = (uint32_t)((gq & 1) * 16);

    const int aRowL = tid >> 3, aC4 = (tid & 7) * 4;
    const int bRowL = tid >> 2, bC8 = (tid & 3) * 8;

    float acc[2][16][4];
    #pragma unroll
    for (int i = 0; i < 2; i++)
        #pragma unroll
        for (int j = 0; j < 16; j++)
            #pragma unroll
            for (int q = 0; q < 4; q++) acc[i][j][q] = 0.f;

    const float* Xb = X + (size_t)by * 128 * MD;

    float4 aReg[4];
    #pragma unroll
    for (int i = 0; i < 4; i++)
        aReg[i] = *(const float4*)(Xb + (size_t)(aRowL + i * 32) * MD + aC4);
    #pragma unroll
    for (int i = 0; i < 4; i++) {
        int row = bRowL + i * 64;
        CP16(sb + G1_B + (uint32_t)(row * 80 + bC8 * 2), g_Wh + (size_t)row * MD + bC8);
    }
    CP_COMMIT();

    // ================= mainloop: single-term fp16 =================
    for (int kc = 0; kc < MD / BK; kc++) {
        const int s = kc & 1;
        char* st = dsm + s * G1_STAGE;
        const uint32_t stu = sb + s * G1_STAGE;

        #pragma unroll
        for (int i = 0; i < 4; i++) {
            float4 v = aReg[i];
            int row = aRowL + i * 32;
            *(uint2*)(st + G1_A + row * 80 + aC4 * 2) =
                make_uint2(pack_h2(v.x, v.y), pack_h2(v.z, v.w));
        }
        CP_WAIT0();
        __syncthreads();

        if (kc + 1 < MD / BK) {
            const int k0n = (kc + 1) * BK;
            #pragma unroll
            for (int i = 0; i < 4; i++)
                aReg[i] = *(const float4*)(Xb + (size_t)(aRowL + i * 32) * MD + k0n + aC4);
            const uint32_t stn = sb + (s ^ 1) * G1_STAGE;
            #pragma unroll
            for (int i = 0; i < 4; i++) {
                int row = bRowL + i * 64;
                CP16(stn + G1_B + (uint32_t)(row * 80 + bC8 * 2),
                     g_Wh + (size_t)row * MD + k0n + bC8);
            }
            CP_COMMIT();
        }

        #pragma unroll
        for (int ks = 0; ks < 2; ks++) {
            uint32_t af[2][4];
            #pragma unroll
            for (int mt = 0; mt < 2; mt++) {
                uint32_t off = (uint32_t)((warpM * 32 + mt * 16 + aRow) * 80) +
                               (uint32_t)(ks * 32) + aByte;
                LDSM4(af[mt][0], af[mt][1], af[mt][2], af[mt][3], stu + G1_A + off);
            }
            #pragma unroll
            for (int p = 0; p < 4; p++) {
                uint32_t bf[2][4];
                #pragma unroll
                for (int j = 0; j < 2; j++) {
                    int nf2 = p * 2 + j;
                    uint32_t off = (uint32_t)((warpN * 128 + nf2 * 16 + bRowBase) * 80) +
                                   (uint32_t)(ks * 32) + bByte;
                    LDSM4(bf[j][0], bf[j][1], bf[j][2], bf[j][3], stu + G1_B + off);
                }
                #pragma unroll
                for (int j = 0; j < 2; j++)
                    #pragma unroll
                    for (int half = 0; half < 2; half++) {
                        int nf = (p * 2 + j) * 2 + half;
                        uint32_t b2[2] = { bf[j][half * 2], bf[j][half * 2 + 1] };
                        #pragma unroll
                        for (int mt = 0; mt < 2; mt++)
                            MMAF16(acc[mt][nf], af[mt], b2);
                    }
            }
        }
    }

    // ================= fused tail (bf16 3-term GEMM2, unchanged from R7) ======
    __syncthreads();

    #pragma unroll
    for (int i = 0; i < 8; i++) {
        int idx = i * 256 + tid;
        int row = idx >> 5, c8 = (idx & 31) * 8;
        *(uint4*)(dsm + SHI_B + row * 528 + c8 * 2) = *(const uint4*)(g_simHi + row * PD + c8);
        *(uint4*)(dsm + SLO_B + row * 528 + c8 * 2) = *(const uint4*)(g_simLo + row * PD + c8);
    }
    ((float*)(dsm + BIAS_B))[tid] = bias[tid];
    if (tid < NE) ((float*)(dsm + MASK_B))[tid] = mask[tid];
    __syncthreads();

    const float* sBias = (const float*)(dsm + BIAS_B);
    const int qr = lane >> 2, qc = (lane & 3) * 2;
    float ss[4] = {0.f, 0.f, 0.f, 0.f};
    #pragma unroll
    for (int mt = 0; mt < 2; mt++)
        #pragma unroll
        for (int nf = 0; nf < 16; nf++) {
            int c = warpN * 128 + nf * 8 + qc;
            float b0 = sBias[c], b1 = sBias[c + 1];
            acc[mt][nf][0] += b0; acc[mt][nf][1] += b1;
            acc[mt][nf][2] += b0; acc[mt][nf][3] += b1;
            ss[mt * 2]     += acc[mt][nf][0] * acc[mt][nf][0] + acc[mt][nf][1] * acc[mt][nf][1];
            ss[mt * 2 + 1] += acc[mt][nf][2] * acc[mt][nf][2] + acc[mt][nf][3] * acc[mt][nf][3];
        }
    #pragma unroll
    for (int sl = 0; sl < 4; sl++) {
        ss[sl] += __shfl_xor_sync(0xffffffffu, ss[sl], 1);
        ss[sl] += __shfl_xor_sync(0xffffffffu, ss[sl], 2);
    }
    if ((lane & 3) == 0) {
        #pragma unroll
        for (int sl = 0; sl < 4; sl++) {
            int row = warpM * 32 + (sl >> 1) * 16 + qr + (sl & 1) * 8;
            ((float*)(dsm + NORM_B))[row * 2 + warpN] = ss[sl];
        }
    }
    __syncthreads();
    if (tid < 128) {
        const float* nb = (const float*)(dsm + NORM_B);
        float tot = nb[tid * 2] + nb[tid * 2 + 1];
        ((float*)(dsm + SINV_B))[tid] = g_scale / fmaxf(sqrtf(tot), 1e-12f);
    }
    __syncthreads();

    // GEMM2: logits partial [32 rows x 64 experts] over this warp's K half
    float acc2[2][8][4];
    #pragma unroll
    for (int i = 0; i < 2; i++)
        #pragma unroll
        for (int j = 0; j < 8; j++)
            #pragma unroll
            for (int q = 0; q < 4; q++) acc2[i][j][q] = 0.f;

    #pragma unroll
    for (int ks = 0; ks < 8; ks++) {
        uint32_t ahi[2][4], alo[2][4];
        #pragma unroll
        for (int mt = 0; mt < 2; mt++) {
            float l0, l1;
            ahi[mt][0] = pack_hi(acc[mt][2 * ks][0], acc[mt][2 * ks][1], l0, l1);
            alo[mt][0] = pack_bf2(l0, l1);
            ahi[mt][1] = pack_hi(acc[mt][2 * ks][2], acc[mt][2 * ks][3], l0, l1);
            alo[mt][1] = pack_bf2(l0, l1);
            ahi[mt][2] = pack_hi(acc[mt][2 * ks + 1][0], acc[mt][2 * ks + 1][1], l0, l1);
            alo[mt][2] = pack_bf2(l0, l1);
            ahi[mt][3] = pack_hi(acc[mt][2 * ks + 1][2], acc[mt][2 * ks + 1][3], l0, l1);
            alo[mt][3] = pack_bf2(l0, l1);
        }
        #pragma unroll
        for (int ne2 = 0; ne2 < 4; ne2++) {
            uint32_t boff = (uint32_t)((ne2 * 16 + bRowBase) * 528) +
                            (uint32_t)((warpN * 8 + ks) * 32) + bByte;
            uint32_t bh[4], bl[4];
            LDSM4(bh[0], bh[1], bh[2], bh[3], sb + SHI_B + boff);
            LDSM4(bl[0], bl[1], bl[2], bl[3], sb + SLO_B + boff);
            #pragma unroll
            for (int half = 0; half < 2; half++)
                #pragma unroll
                for (int mt = 0; mt < 2; mt++) {
                    uint32_t b2[2] = { bh[half * 2], bh[half * 2 + 1] };
                    MMAB16(acc2[mt][ne2 * 2 + half], ahi[mt], b2);
                }
            #pragma unroll
            for (int half = 0; half < 2; half++)
                #pragma unroll
                for (int mt = 0; mt < 2; mt++) {
                    uint32_t b2[2] = { bl[half * 2], bl[half * 2 + 1] };
                    MMAB16(acc2[mt][ne2 * 2 + half], ahi[mt], b2);
                }
            #pragma unroll
            for (int half = 0; half < 2; half++)
                #pragma unroll
                for (int mt = 0; mt < 2; mt++) {
                    uint32_t b2[2] = { bh[half * 2], bh[half * 2 + 1] };
                    MMAB16(acc2[mt][ne2 * 2 + half], alo[mt], b2);
                }
        }
    }

    if (warpN == 1) {
        float* cb = (float*)(dsm + CBUF_B);
        #pragma unroll
        for (int mt = 0; mt < 2; mt++)
            #pragma unroll
            for (int nf = 0; nf < 8; nf++) {
                int r = warpM * 32 + mt * 16 + qr;
                int c = nf * 8 + qc;
                *(float2*)(cb + r * 68 + c)       = make_float2(acc2[mt][nf][0], acc2[mt][nf][1]);
                *(float2*)(cb + (r + 8) * 68 + c) = make_float2(acc2[mt][nf][2], acc2[mt][nf][3]);
            }
    }
    __syncthreads();

    if (warpN == 0) {
        const float* cb = (const float*)(dsm + CBUF_B);
        const float* sInv = (const float*)(dsm + SINV_B);
        const float* sMask = (const float*)(dsm + MASK_B);
        float* sc = (float*)(dsm + SCBUF_B);
        #pragma unroll
        for (int mt = 0; mt < 2; mt++) {
            int r0 = warpM * 32 + mt * 16 + qr, r1 = r0 + 8;
            float inv0 = sInv[r0], inv1 = sInv[r1];
            float p0[16], p1[16];
            #pragma unroll
            for (int nf = 0; nf < 8; nf++) {
                int c = nf * 8 + qc;
                float2 c0 = *(const float2*)(cb + r0 * 68 + c);
                float2 c1 = *(const float2*)(cb + r1 * 68 + c);
                bool m0 = sMask[c] == 0.f, m1 = sMask[c + 1] == 0.f;
                float a  = m0 ? -1e9f : (acc2[mt][nf][0] + c0.x) * inv0;
                float b  = m1 ? -1e9f : (acc2[mt][nf][1] + c0.y) * inv0;
                float cc = m0 ? -1e9f : (acc2[mt][nf][2] + c1.x) * inv1;
                float dd = m1 ? -1e9f : (acc2[mt][nf][3] + c1.y) * inv1;
                p0[nf * 2] = a;  p0[nf * 2 + 1] = b;
                p1[nf * 2] = cc; p1[nf * 2 + 1] = dd;
                *(float2*)(out_logits + (size_t)(tokBase + r0) * NE + c) = make_float2(a, b);
                *(float2*)(out_logits + (size_t)(tokBase + r1) * NE + c) = make_float2(cc, dd);
            }
            if (write_topk) {
                float m0 = -1e30f, m1 = -1e30f;
                #pragma unroll
                for (int j = 0; j < 16; j++) { m0 = fmaxf(m0, p0[j]); m1 = fmaxf(m1, p1[j]); }
                #pragma unroll
                for (int o = 1; o < 4; o <<= 1) {
                    m0 = fmaxf(m0, __shfl_xor_sync(0xffffffffu, m0, o));
                    m1 = fmaxf(m1, __shfl_xor_sync(0xffffffffu, m1, o));
                }
                float s0 = 0.f, s1 = 0.f;
                #pragma unroll
                for (int j = 0; j < 16; j++) {
                    p0[j] = __expf(p0[j] - m0); s0 += p0[j];
                    p1[j] = __expf(p1[j] - m1); s1 += p1[j];
                }
                #pragma unroll
                for (int o = 1; o < 4; o <<= 1) {
                    s0 += __shfl_xor_sync(0xffffffffu, s0, o);
                    s1 += __shfl_xor_sync(0xffffffffu, s1, o);
                }
                float is0 = 1.f / s0, is1 = 1.f / s1;
                #pragma unroll
                for (int nf = 0; nf < 8; nf++) {
                    int c = nf * 8 + qc;
                    *(float2*)(sc + r0 * 68 + c) =
                        make_float2(p0[nf * 2] * is0 + 1e-14f, p0[nf * 2 + 1] * is0 + 1e-14f);
                    *(float2*)(sc + r1 * 68 + c) =
                        make_float2(p1[nf * 2] * is1 + 1e-14f, p1[nf * 2 + 1] * is1 + 1e-14f);
                }
            }
        }
    }
    __syncthreads();

    if (write_topk && tid < 128) {
        const float* row = (const float*)(dsm + SCBUF_B) + tid * 68;
        float v[64];
        #pragma unroll
        for (int i = 0; i < 16; i++)
            *(float4*)(v + i * 4) = *(const float4*)(row + i * 4);
        #pragma unroll
        for (int k = 2; k <= 64; k <<= 1)
            #pragma unroll
            for (int j = k >> 1; j > 0; j >>= 1)
                #pragma unroll
                for (int i = 0; i < 64; i++) {
                    int p = i ^ j;
                    if (p > i) {
                        bool up = ((i & k) == 0);
                        float a = v[i], b = v[p];
                        bool sw = up ? (a > b) : (a < b);
                        float lo = sw ? b : a, hi = sw ? a : b;
                        v[i] = lo; v[p] = hi;
                    }
                }
        float cum = 0.f; int k = 0;
        #pragma unroll
        for (int r = 63; r >= 0; r--) { if (cum < 1.f) k++; cum += v[r]; }
        out_topk[tokBase + tid] = fminf((float)k, g_active);
    }
}

// ---------------- launch ----------------
extern "C" void kernel_launch(void* const* d_in, const int* in_sizes, int n_in,
                              void* d_out, int out_size) {
    const float* x    = (const float*)d_in[0];
    const float* W    = (const float*)d_in[1];
    const float* b    = (const float*)d_in[2];
    const float* sim  = (const float*)d_in[3];
    const float* temp = (const float*)d_in[4];
    const float* mask = (const float*)d_in[5];
    float* out = (float*)d_out;

    cudaFuncSetAttribute(fused_kernel, cudaFuncAttributeMaxDynamicSharedMemorySize, SMEM_TOTAL);

    convert_w_kernel<<<512, 256>>>(W);
    prep_kernel<<<1, 64>>>(sim, temp, mask);

    const int logits_elems = NTOK * NE;
    int write_topk = (out_size >= logits_elems + NTOK) ? 1 : 0;
    fused_kernel<<<NTOK / 128, 256, SMEM_TOTAL>>>(x, b, mask, out, out + logits_elems, write_topk);
}

// round 14
// speedup vs baseline: 5.0221x; 1.2288x over previous
#include <cuda_runtime.h>
#include <cuda_bf16.h>
#include <cuda_fp16.h>
#include <cstdint>

#define NTOK 16384
#define MD   2048
#define PD   256
#define NE   64
#define BK   32

// ---------------- device globals ----------------
__device__ __align__(16) __half g_Wh[PD * MD];
__device__ __align__(16) __nv_bfloat16 g_simHi[NE * PD];
__device__ __align__(16) __nv_bfloat16 g_simLo[NE * PD];
__device__ float g_scale;
__device__ float g_active;

// ---------------- helpers ----------------
__device__ __forceinline__ uint32_t smem_u32(const void* p) {
    uint32_t a;
    asm("{ .reg .u64 t; cvta.to.shared.u64 t, %1; cvt.u32.u64 %0, t; }" : "=r"(a) : "l"(p));
    return a;
}
#define LDSM4(r0, r1, r2, r3, a)                                                  \
    asm volatile("ldmatrix.sync.aligned.m8n8.x4.shared.b16 {%0,%1,%2,%3}, [%4];" \
                 : "=r"(r0), "=r"(r1), "=r"(r2), "=r"(r3) : "r"(a))
#define MMAB16(c, a, b)                                                           \
    asm volatile("mma.sync.aligned.m16n8k16.row.col.f32.bf16.bf16.f32 "           \
                 "{%0,%1,%2,%3}, {%4,%5,%6,%7}, {%8,%9}, {%0,%1,%2,%3};"          \
                 : "+f"((c)[0]), "+f"((c)[1]), "+f"((c)[2]), "+f"((c)[3])         \
                 : "r"((a)[0]), "r"((a)[1]), "r"((a)[2]), "r"((a)[3]),            \
                   "r"((b)[0]), "r"((b)[1]))
#define MMAF16(c, a, b)                                                           \
    asm volatile("mma.sync.aligned.m16n8k16.row.col.f32.f16.f16.f32 "             \
                 "{%0,%1,%2,%3}, {%4,%5,%6,%7}, {%8,%9}, {%0,%1,%2,%3};"          \
                 : "+f"((c)[0]), "+f"((c)[1]), "+f"((c)[2]), "+f"((c)[3])         \
                 : "r"((a)[0]), "r"((a)[1]), "r"((a)[2]), "r"((a)[3]),            \
                   "r"((b)[0]), "r"((b)[1]))
#define CP16(dst, src) asm volatile("cp.async.cg.shared.global [%0], [%1], 16;" :: "r"(dst), "l"(src))
#define CP_COMMIT()    asm volatile("cp.async.commit_group;" ::: "memory")
#define CP_WAIT0()     asm volatile("cp.async.wait_group 0;" ::: "memory")

__device__ __forceinline__ uint32_t pack_h2(float a, float b) {
    __half2 t = __floats2half2_rn(a, b);
    return *reinterpret_cast<uint32_t*>(&t);
}
__device__ __forceinline__ uint32_t pack_hi(float v0, float v1, float& l0, float& l1) {
    __nv_bfloat16 h0 = __float2bfloat16(v0), h1 = __float2bfloat16(v1);
    l0 = v0 - __bfloat162float(h0);
    l1 = v1 - __bfloat162float(h1);
    return (uint32_t)__bfloat16_as_ushort(h0) | ((uint32_t)__bfloat16_as_ushort(h1) << 16);
}
__device__ __forceinline__ uint32_t pack_bf2(float v0, float v1) {
    return (uint32_t)__bfloat16_as_ushort(__float2bfloat16(v0)) |
           ((uint32_t)__bfloat16_as_ushort(__float2bfloat16(v1)) << 16);
}

// ---------------- prep: W convert (blocks 0..511) + sim normalize (blocks 512..519) ----
__global__ void prep_all_kernel(const float* __restrict__ W,
                                const float* __restrict__ sim,
                                const float* __restrict__ temperature,
                                const float* __restrict__ mask) {
    if (blockIdx.x < 512) {
        int i = blockIdx.x * 256 + threadIdx.x;     // 131072 float4 chunks
        float4 v = ((const float4*)W)[i];
        ((uint2*)g_Wh)[i] = make_uint2(pack_h2(v.x, v.y), pack_h2(v.z, v.w));
        return;
    }
    // prep path: 8 blocks x 8 warps = 64 warps, one per expert
    int wg = (blockIdx.x - 512) * 8 + (threadIdx.x >> 5);   // expert 0..63
    int lane = threadIdx.x & 31;
    float vals[8];
    float ss = 0.f;
    #pragma unroll
    for (int j = 0; j < 8; j++) {
        float v = sim[(lane + 32 * j) * NE + wg];
        vals[j] = v;
        ss += v * v;
    }
    #pragma unroll
    for (int o = 16; o > 0; o >>= 1) ss += __shfl_xor_sync(0xffffffffu, ss, o);
    float inv = 1.f / fmaxf(sqrtf(ss), 1e-12f);
    #pragma unroll
    for (int j = 0; j < 8; j++) {
        float v = vals[j] * inv;
        __nv_bfloat16 h = __float2bfloat16(v);
        g_simHi[wg * PD + lane + 32 * j] = h;
        g_simLo[wg * PD + lane + 32 * j] = __float2bfloat16(v - __bfloat162float(h));
    }
    if (blockIdx.x == 512 && threadIdx.x == 0) {
        float a = 0.f;
        for (int i = 0; i < NE; i++) a += mask[i];
        g_active = a;
        g_scale = expf(fminf(temperature[0], 4.6051701859880913680f));
    }
}

// ---------------- smem layout (bytes) ----------------
// mainloop: 2 stages of (A 10240 | B 20480)
#define G1_A 0
#define G1_B 10240
#define G1_STAGE 30720
// tail overlay:
#define SHI_B   0          // sim hi: 64 rows x 264 elems x 2B = 33792
#define SLO_B   33792
#define CBUF_B  67584      // 128 x 68 f32 = 34816
#define SCBUF_B 102400     // 128 x 68 f32 = 34816 (end 137216)
#define BIAS_B  137216     // 256 f32
#define MASK_B  138240     // 64 f32
#define NORM_B  138496     // 128 x 2 f32
#define SINV_B  139520     // 128 f32
#define SMEM_TOTAL 140032

// ---------------- fused kernel ----------------
__global__ void __launch_bounds__(256, 1)
fused_kernel(const float* __restrict__ X, const float* __restrict__ bias,
             const float* __restrict__ mask,
             float* __restrict__ out_logits, float* __restrict__ out_topk,
             int write_topk) {
    extern __shared__ __align__(16) char dsm[];
    const uint32_t sb = smem_u32(dsm);

    const int tid = threadIdx.x;
    const int wid = tid >> 5, lane = tid & 31;
    const int warpM = wid & 3;    // 4 x 32 rows
    const int warpN = wid >> 2;   // 2 x 128 cols
    const int by = blockIdx.x;
    const int tokBase = by * 128;

    const uint32_t aRow  = (uint32_t)(lane & 15);
    const uint32_t aByte = (uint32_t)((lane >> 4) * 16);
    const int gq = lane >> 3;
    const uint32_t bRowBase = (uint32_t)(((gq >> 1) << 3) + (lane & 7));
    const uint32_t bByte = (uint32_t)((gq & 1) * 16);

    const int aRowL = tid >> 3, aC4 = (tid & 7) * 4;
    const int bRowL = tid >> 2, bC8 = (tid & 3) * 8;

    float acc[2][16][4];
    #pragma unroll
    for (int i = 0; i < 2; i++)
        #pragma unroll
        for (int j = 0; j < 16; j++)
            #pragma unroll
            for (int q = 0; q < 4; q++) acc[i][j][q] = 0.f;

    const float* Xb = X + (size_t)by * 128 * MD;

    // prologue: A(0) load+convert+STS into stage 0; cp.async B(0) -> stage 0
    float4 aReg[4];
    #pragma unroll
    for (int i = 0; i < 4; i++)
        aReg[i] = *(const float4*)(Xb + (size_t)(aRowL + i * 32) * MD + aC4);
    #pragma unroll
    for (int i = 0; i < 4; i++) {
        float4 v = aReg[i];
        int row = aRowL + i * 32;
        *(uint2*)(dsm + G1_A + row * 80 + aC4 * 2) =
            make_uint2(pack_h2(v.x, v.y), pack_h2(v.z, v.w));
    }
    #pragma unroll
    for (int i = 0; i < 4; i++) {
        int row = bRowL + i * 64;
        CP16(sb + G1_B + (uint32_t)(row * 80 + bC8 * 2), g_Wh + (size_t)row * MD + bC8);
    }
    CP_COMMIT();

    // ================= mainloop: single-term fp16, convert hidden under MMA ====
    for (int kc = 0; kc < MD / BK; kc++) {
        const int s = kc & 1;
        const uint32_t stu = sb + s * G1_STAGE;
        char* stn = dsm + (s ^ 1) * G1_STAGE;
        const bool nxt = (kc + 1 < MD / BK);

        CP_WAIT0();
        __syncthreads();   // stage s ready; stage s^1 free (all warps done MMA(kc-1))

        if (nxt) {
            const int k0n = (kc + 1) * BK;
            // issue next B into stage s^1
            #pragma unroll
            for (int i = 0; i < 4; i++) {
                int row = bRowL + i * 64;
                CP16(sb + (s ^ 1) * G1_STAGE + G1_B + (uint32_t)(row * 80 + bC8 * 2),
                     g_Wh + (size_t)row * MD + k0n + bC8);
            }
            CP_COMMIT();
            // issue next A loads (consumed late in the MMA phase)
            #pragma unroll
            for (int i = 0; i < 4; i++)
                aReg[i] = *(const float4*)(Xb + (size_t)(aRowL + i * 32) * MD + k0n + aC4);
        }

        #pragma unroll
        for (int ks = 0; ks < 2; ks++) {
            uint32_t af[2][4];
            #pragma unroll
            for (int mt = 0; mt < 2; mt++) {
                uint32_t off = (uint32_t)((warpM * 32 + mt * 16 + aRow) * 80) +
                               (uint32_t)(ks * 32) + aByte;
                LDSM4(af[mt][0], af[mt][1], af[mt][2], af[mt][3], stu + G1_A + off);
            }
            #pragma unroll
            for (int p = 0; p < 4; p++) {
                uint32_t bf[2][4];
                #pragma unroll
                for (int j = 0; j < 2; j++) {
                    int nf2 = p * 2 + j;
                    uint32_t off = (uint32_t)((warpN * 128 + nf2 * 16 + bRowBase) * 80) +
                                   (uint32_t)(ks * 32) + bByte;
                    LDSM4(bf[j][0], bf[j][1], bf[j][2], bf[j][3], stu + G1_B + off);
                }
                #pragma unroll
                for (int j = 0; j < 2; j++)
                    #pragma unroll
                    for (int half = 0; half < 2; half++) {
                        int nf = (p * 2 + j) * 2 + half;
                        uint32_t b2[2] = { bf[j][half * 2], bf[j][half * 2 + 1] };
                        #pragma unroll
                        for (int mt = 0; mt < 2; mt++)
                            MMAF16(acc[mt][nf], af[mt], b2);
                    }
                // interleave next-A convert+STS into the 2nd half of the MMA phase
                if (ks == 1 && nxt) {
                    float4 v = aReg[p];
                    int row = aRowL + p * 32;
                    *(uint2*)(stn + G1_A + row * 80 + aC4 * 2) =
                        make_uint2(pack_h2(v.x, v.y), pack_h2(v.z, v.w));
                }
            }
        }
    }

    // ================= fused tail (bf16 3-term GEMM2) ======
    __syncthreads();

    #pragma unroll
    for (int i = 0; i < 8; i++) {
        int idx = i * 256 + tid;
        int row = idx >> 5, c8 = (idx & 31) * 8;
        *(uint4*)(dsm + SHI_B + row * 528 + c8 * 2) = *(const uint4*)(g_simHi + row * PD + c8);
        *(uint4*)(dsm + SLO_B + row * 528 + c8 * 2) = *(const uint4*)(g_simLo + row * PD + c8);
    }
    ((float*)(dsm + BIAS_B))[tid] = bias[tid];
    if (tid < NE) ((float*)(dsm + MASK_B))[tid] = mask[tid];
    __syncthreads();

    const float* sBias = (const float*)(dsm + BIAS_B);
    const int qr = lane >> 2, qc = (lane & 3) * 2;
    float ss[4] = {0.f, 0.f, 0.f, 0.f};
    #pragma unroll
    for (int mt = 0; mt < 2; mt++)
        #pragma unroll
        for (int nf = 0; nf < 16; nf++) {
            int c = warpN * 128 + nf * 8 + qc;
            float b0 = sBias[c], b1 = sBias[c + 1];
            acc[mt][nf][0] += b0; acc[mt][nf][1] += b1;
            acc[mt][nf][2] += b0; acc[mt][nf][3] += b1;
            ss[mt * 2]     += acc[mt][nf][0] * acc[mt][nf][0] + acc[mt][nf][1] * acc[mt][nf][1];
            ss[mt * 2 + 1] += acc[mt][nf][2] * acc[mt][nf][2] + acc[mt][nf][3] * acc[mt][nf][3];
        }
    #pragma unroll
    for (int sl = 0; sl < 4; sl++) {
        ss[sl] += __shfl_xor_sync(0xffffffffu, ss[sl], 1);
        ss[sl] += __shfl_xor_sync(0xffffffffu, ss[sl], 2);
    }
    if ((lane & 3) == 0) {
        #pragma unroll
        for (int sl = 0; sl < 4; sl++) {
            int row = warpM * 32 + (sl >> 1) * 16 + qr + (sl & 1) * 8;
            ((float*)(dsm + NORM_B))[row * 2 + warpN] = ss[sl];
        }
    }
    __syncthreads();
    if (tid < 128) {
        const float* nb = (const float*)(dsm + NORM_B);
        float tot = nb[tid * 2] + nb[tid * 2 + 1];
        ((float*)(dsm + SINV_B))[tid] = g_scale / fmaxf(sqrtf(tot), 1e-12f);
    }
    __syncthreads();

    float acc2[2][8][4];
    #pragma unroll
    for (int i = 0; i < 2; i++)
        #pragma unroll
        for (int j = 0; j < 8; j++)
            #pragma unroll
            for (int q = 0; q < 4; q++) acc2[i][j][q] = 0.f;

    #pragma unroll
    for (int ks = 0; ks < 8; ks++) {
        uint32_t ahi[2][4], alo[2][4];
        #pragma unroll
        for (int mt = 0; mt < 2; mt++) {
            float l0, l1;
            ahi[mt][0] = pack_hi(acc[mt][2 * ks][0], acc[mt][2 * ks][1], l0, l1);
            alo[mt][0] = pack_bf2(l0, l1);
            ahi[mt][1] = pack_hi(acc[mt][2 * ks][2], acc[mt][2 * ks][3], l0, l1);
            alo[mt][1] = pack_bf2(l0, l1);
            ahi[mt][2] = pack_hi(acc[mt][2 * ks + 1][0], acc[mt][2 * ks + 1][1], l0, l1);
            alo[mt][2] = pack_bf2(l0, l1);
            ahi[mt][3] = pack_hi(acc[mt][2 * ks + 1][2], acc[mt][2 * ks + 1][3], l0, l1);
            alo[mt][3] = pack_bf2(l0, l1);
        }
        #pragma unroll
        for (int ne2 = 0; ne2 < 4; ne2++) {
            uint32_t boff = (uint32_t)((ne2 * 16 + bRowBase) * 528) +
                            (uint32_t)((warpN * 8 + ks) * 32) + bByte;
            uint32_t bh[4], bl[4];
            LDSM4(bh[0], bh[1], bh[2], bh[3], sb + SHI_B + boff);
            LDSM4(bl[0], bl[1], bl[2], bl[3], sb + SLO_B + boff);
            #pragma unroll
            for (int half = 0; half < 2; half++)
                #pragma unroll
                for (int mt = 0; mt < 2; mt++) {
                    uint32_t b2[2] = { bh[half * 2], bh[half * 2 + 1] };
                    MMAB16(acc2[mt][ne2 * 2 + half], ahi[mt], b2);
                }
            #pragma unroll
            for (int half = 0; half < 2; half++)
                #pragma unroll
                for (int mt = 0; mt < 2; mt++) {
                    uint32_t b2[2] = { bl[half * 2], bl[half * 2 + 1] };
                    MMAB16(acc2[mt][ne2 * 2 + half], ahi[mt], b2);
                }
            #pragma unroll
            for (int half = 0; half < 2; half++)
                #pragma unroll
                for (int mt = 0; mt < 2; mt++) {
                    uint32_t b2[2] = { bh[half * 2], bh[half * 2 + 1] };
                    MMAB16(acc2[mt][ne2 * 2 + half], alo[mt], b2);
                }
        }
    }

    if (warpN == 1) {
        float* cb = (float*)(dsm + CBUF_B);
        #pragma unroll
        for (int mt = 0; mt < 2; mt++)
            #pragma unroll
            for (int nf = 0; nf < 8; nf++) {
                int r = warpM * 32 + mt * 16 + qr;
                int c = nf * 8 + qc;
                *(float2*)(cb + r * 68 + c)       = make_float2(acc2[mt][nf][0], acc2[mt][nf][1]);
                *(float2*)(cb + (r + 8) * 68 + c) = make_float2(acc2[mt][nf][2], acc2[mt][nf][3]);
            }
    }
    __syncthreads();

    if (warpN == 0) {
        const float* cb = (const float*)(dsm + CBUF_B);
        const float* sInv = (const float*)(dsm + SINV_B);
        const float* sMask = (const float*)(dsm + MASK_B);
        float* sc = (float*)(dsm + SCBUF_B);
        #pragma unroll
        for (int mt = 0; mt < 2; mt++) {
            int r0 = warpM * 32 + mt * 16 + qr, r1 = r0 + 8;
            float inv0 = sInv[r0], inv1 = sInv[r1];
            float p0[16], p1[16];
            #pragma unroll
            for (int nf = 0; nf < 8; nf++) {
                int c = nf * 8 + qc;
                float2 c0 = *(const float2*)(cb + r0 * 68 + c);
                float2 c1 = *(const float2*)(cb + r1 * 68 + c);
                bool m0 = sMask[c] == 0.f, m1 = sMask[c + 1] == 0.f;
                float a  = m0 ? -1e9f : (acc2[mt][nf][0] + c0.x) * inv0;
                float b  = m1 ? -1e9f : (acc2[mt][nf][1] + c0.y) * inv0;
                float cc = m0 ? -1e9f : (acc2[mt][nf][2] + c1.x) * inv1;
                float dd = m1 ? -1e9f : (acc2[mt][nf][3] + c1.y) * inv1;
                p0[nf * 2] = a;  p0[nf * 2 + 1] = b;
                p1[nf * 2] = cc; p1[nf * 2 + 1] = dd;
                *(float2*)(out_logits + (size_t)(tokBase + r0) * NE + c) = make_float2(a, b);
                *(float2*)(out_logits + (size_t)(tokBase + r1) * NE + c) = make_float2(cc, dd);
            }
            if (write_topk) {
                float m0 = -1e30f, m1 = -1e30f;
                #pragma unroll
                for (int j = 0; j < 16; j++) { m0 = fmaxf(m0, p0[j]); m1 = fmaxf(m1, p1[j]); }
                #pragma unroll
                for (int o = 1; o < 4; o <<= 1) {
                    m0 = fmaxf(m0, __shfl_xor_sync(0xffffffffu, m0, o));
                    m1 = fmaxf(m1, __shfl_xor_sync(0xffffffffu, m1, o));
                }
                float s0 = 0.f, s1 = 0.f;
                #pragma unroll
                for (int j = 0; j < 16; j++) {
                    p0[j] = __expf(p0[j] - m0); s0 += p0[j];
                    p1[j] = __expf(p1[j] - m1); s1 += p1[j];
                }
                #pragma unroll
                for (int o = 1; o < 4; o <<= 1) {
                    s0 += __shfl_xor_sync(0xffffffffu, s0, o);
                    s1 += __shfl_xor_sync(0xffffffffu, s1, o);
                }
                float is0 = 1.f / s0, is1 = 1.f / s1;
                #pragma unroll
                for (int nf = 0; nf < 8; nf++) {
                    int c = nf * 8 + qc;
                    *(float2*)(sc + r0 * 68 + c) =
                        make_float2(p0[nf * 2] * is0 + 1e-14f, p0[nf * 2 + 1] * is0 + 1e-14f);
                    *(float2*)(sc + r1 * 68 + c) =
                        make_float2(p1[nf * 2] * is1 + 1e-14f, p1[nf * 2 + 1] * is1 + 1e-14f);
                }
            }
        }
    }
    __syncthreads();

    if (write_topk && tid < 128) {
        const float* row = (const float*)(dsm + SCBUF_B) + tid * 68;
        float v[64];
        #pragma unroll
        for (int i = 0; i < 16; i++)
            *(float4*)(v + i * 4) = *(const float4*)(row + i * 4);
        #pragma unroll
        for (int k = 2; k <= 64; k <<= 1)
            #pragma unroll
            for (int j = k >> 1; j > 0; j >>= 1)
                #pragma unroll
                for (int i = 0; i < 64; i++) {
                    int p = i ^ j;
                    if (p > i) {
                        bool up = ((i & k) == 0);
                        float a = v[i], b = v[p];
                        bool sw = up ? (a > b) : (a < b);
                        float lo = sw ? b : a, hi = sw ? a : b;
                        v[i] = lo; v[p] = hi;
                    }
                }
        float cum = 0.f; int k = 0;
        #pragma unroll
        for (int r = 63; r >= 0; r--) { if (cum < 1.f) k++; cum += v[r]; }
        out_topk[tokBase + tid] = fminf((float)k, g_active);
    }
}

// ---------------- launch ----------------
extern "C" void kernel_launch(void* const* d_in, const int* in_sizes, int n_in,
                              void* d_out, int out_size) {
    const float* x    = (const float*)d_in[0];
    const float* W    = (const float*)d_in[1];
    const float* b    = (const float*)d_in[2];
    const float* sim  = (const float*)d_in[3];
    const float* temp = (const float*)d_in[4];
    const float* mask = (const float*)d_in[5];
    float* out = (float*)d_out;

    cudaFuncSetAttribute(fused_kernel, cudaFuncAttributeMaxDynamicSharedMemorySize, SMEM_TOTAL);

    prep_all_kernel<<<520, 256>>>(W, sim, temp, mask);

    const int logits_elems = NTOK * NE;
    int write_topk = (out_size >= logits_elems + NTOK) ? 1 : 0;
    fused_kernel<<<NTOK / 128, 256, SMEM_TOTAL>>>(x, b, mask, out, out + logits_elems, write_topk);
}